// round 9
// baseline (speedup 1.0000x reference)
#include <cuda_runtime.h>
#include <cuda_bf16.h>
#include <math.h>

#define NROWS 65536
#define EDIM  1024
#define KST   4
#define DDIM  5

// ---- device scratch / constants (no allocations allowed) ----
__device__ float g_shift[5];
__device__ float g_half_l[5];
__device__ float g_off_b[5];
__device__ float g_halfw[5];
__device__ float g_row_norm[NROWS];

__constant__ int c_lo[5] = {0, 0, 0, 1, 2};   // valid step index range per dim
__constant__ int c_hi[5] = {7, 7, 7, 6, 6};   // steps = idx - 4  ->  [-4..3]

// ---- prep: compute bound constants in double, matching numpy f64 -> f32 ----
__global__ void qprep() {
    int t = threadIdx.x;
    if (t < 5) {
        const double lev[5] = {8.0, 8.0, 8.0, 6.0, 5.0};
        double half_l = (lev[t] - 1.0) * (1.0 - 1e-3) / 2.0;
        int li = (int)lev[t];
        double off_b = (li % 2 == 1) ? 0.0 : 0.5;
        g_half_l[t] = (float)half_l;
        g_off_b[t]  = (float)off_b;
        g_shift[t]  = (float)tan(off_b / half_l);
        g_halfw[t]  = (float)(li / 2);
    }
}

// ---- main fused kernel: one block per row, 256 threads, 4 e-dims/thread ----
__global__ __launch_bounds__(256) void qmain(
    const float* __restrict__ h_in,
    const float* __restrict__ Wp,     // (K, D, E)
    const float* __restrict__ bp,     // (K, D)
    const float* __restrict__ Wi,     // (K, E, D)
    const float* __restrict__ bi,     // (K, E)
    const float* __restrict__ temp,   // (1,)
    const float* __restrict__ u,      // (K, N, D, C)
    const float* __restrict__ p,      // (N,)
    float* __restrict__ out_q,        // (N, E)
    float* __restrict__ out_code)     // (N, K*D)
{
    const int row  = blockIdx.x;
    const int t    = threadIdx.x;
    const int lane = t & 31;
    const int warp = t >> 5;

    __shared__ float sh_red[8][5];
    __shared__ float sh_z[5];
    __shared__ float sh_ssq[8];

    // load residual (= h_in row), coalesced float4
    float4 rv = ((const float4*)(h_in + (size_t)row * EDIM))[t];
    float r0 = rv.x, r1 = rv.y, r2 = rv.z, r3 = rv.w;
    float q0 = 0.f, q1 = 0.f, q2 = 0.f, q3 = 0.f;
    float hh = r0*r0 + r1*r1 + r2*r2 + r3*r3;   // for p==0 fallback

    const float pr = p[row];
    float te = temp[0];
    te = fmaxf(te * te, 1e-8f);
    const float inv_t2 = 1.0f / (te * te);      // logits = -d2 / temp_eff^2

    float ssq_sel = 0.f;
    bool  any_sel = false;

    #pragma unroll
    for (int i = 0; i < KST; i++) {
        // ---- projection partials: h_i[d] = sum_e Wp[i][d][e] * r[e] ----
        float pd[5];
        const float* wpbase = Wp + (size_t)i * DDIM * EDIM;
        #pragma unroll
        for (int d = 0; d < 5; d++) {
            float4 w = *(const float4*)(wpbase + d * EDIM + 4 * t);
            pd[d] = w.x*r0 + w.y*r1 + w.z*r2 + w.w*r3;
        }
        #pragma unroll
        for (int d = 0; d < 5; d++) {
            #pragma unroll
            for (int off = 16; off; off >>= 1)
                pd[d] += __shfl_xor_sync(0xffffffffu, pd[d], off);
        }
        if (lane == 0) {
            #pragma unroll
            for (int d = 0; d < 5; d++) sh_red[warp][d] = pd[d];
        }
        __syncthreads();

        // ---- quantize (lanes 0..4 of warp 0 handle one dim each) ----
        if (t < 5) {
            const int d = t;
            float h = bp[i * DDIM + d];
            #pragma unroll
            for (int w = 0; w < 8; w++) h += sh_red[w][d];

            // bound()
            float z = tanhf(h + g_shift[d]) * g_half_l[d] - g_off_b[d];

            // gumbel-max categorical over valid steps (masked steps can never win)
            const float* ub = u + ((((size_t)i * NROWS + row) * DDIM + d) << 3);
            const int lo = c_lo[d], hi = c_hi[d];
            float best = -INFINITY;
            int bc = lo;
            #pragma unroll
            for (int c = 0; c < 8; c++) {
                if (c >= lo && c <= hi) {
                    float uu = ub[c];
                    float g  = -logf(-logf(uu + 1e-20f) + 1e-20f);
                    float df = z - (float)(c - 4);
                    float val = -(df * df) * inv_t2 + g;
                    if (val > best) { best = val; bc = c; }   // first-max tie-break
                }
            }
            float zq = (float)(bc - 4) / g_halfw[d];
            sh_z[d] = zq;
            out_code[(size_t)row * (KST * DDIM) + i * DDIM + d] = zq;
        }
        __syncthreads();

        // ---- inverse projection: q_i[e] = bi[e] + sum_d Wi[i][e][d] * z[d] ----
        const float z0 = sh_z[0], z1 = sh_z[1], z2 = sh_z[2], z3 = sh_z[3], z4 = sh_z[4];
        const float* wib = Wi + (size_t)i * EDIM * DDIM + (size_t)(4 * t) * DDIM; // 20 contiguous floats
        float4 a  = ((const float4*)wib)[0];
        float4 b  = ((const float4*)wib)[1];
        float4 cc = ((const float4*)wib)[2];
        float4 dd = ((const float4*)wib)[3];
        float4 ee = ((const float4*)wib)[4];
        float4 bv = *(const float4*)(bi + (size_t)i * EDIM + 4 * t);

        float qi0 = bv.x + a.x*z0  + a.y*z1  + a.z*z2  + a.w*z3  + b.x*z4;
        float qi1 = bv.y + b.y*z0  + b.z*z1  + b.w*z2  + cc.x*z3 + cc.y*z4;
        float qi2 = bv.z + cc.z*z0 + cc.w*z1 + dd.x*z2 + dd.y*z3 + dd.z*z4;
        float qi3 = bv.w + dd.w*z0 + ee.x*z1 + ee.y*z2 + ee.z*z3 + ee.w*z4;

        r0 -= qi0; r1 -= qi1; r2 -= qi2; r3 -= qi3;
        q0 += qi0; q1 += qi1; q2 += qi2; q3 += qi3;

        // loss selection: h_in - q_mix == residual right after selected stage
        bool sel = (((float)i * 0.25f) < pr) && (pr <= ((float)(i + 1) * 0.25f));
        if (sel) {
            ssq_sel = r0*r0 + r1*r1 + r2*r2 + r3*r3;
            any_sel = true;
        }
    }

    // ---- per-row norm ----
    float ss = any_sel ? ssq_sel : hh;
    #pragma unroll
    for (int off = 16; off; off >>= 1)
        ss += __shfl_xor_sync(0xffffffffu, ss, off);
    if (lane == 0) sh_ssq[warp] = ss;
    __syncthreads();
    if (t == 0) {
        float tot = 0.f;
        #pragma unroll
        for (int w = 0; w < 8; w++) tot += sh_ssq[w];
        g_row_norm[row] = sqrtf(tot);
    }

    // ---- write q ----
    float4 qv = make_float4(q0, q1, q2, q3);
    ((float4*)(out_q + (size_t)row * EDIM))[t] = qv;
}

// ---- deterministic mean of per-row norms ----
__global__ __launch_bounds__(1024) void qfinal(float* __restrict__ out_loss) {
    __shared__ float sh[1024];
    float s = 0.f;
    for (int idx = threadIdx.x; idx < NROWS; idx += 1024) s += g_row_norm[idx];
    sh[threadIdx.x] = s;
    __syncthreads();
    for (int stride = 512; stride; stride >>= 1) {
        if (threadIdx.x < (unsigned)stride) sh[threadIdx.x] += sh[threadIdx.x + stride];
        __syncthreads();
    }
    if (threadIdx.x == 0) out_loss[0] = sh[0] / (float)NROWS;
}

extern "C" void kernel_launch(void* const* d_in, const int* in_sizes, int n_in,
                              void* d_out, int out_size) {
    const float* h_in = (const float*)d_in[0];
    const float* Wp   = (const float*)d_in[1];
    const float* bp   = (const float*)d_in[2];
    const float* Wi   = (const float*)d_in[3];
    const float* bi   = (const float*)d_in[4];
    const float* temp = (const float*)d_in[5];
    const float* u    = (const float*)d_in[6];
    const float* p    = (const float*)d_in[7];

    float* out      = (float*)d_out;
    float* out_q    = out;                                   // (N, E)
    float* out_code = out + (size_t)NROWS * EDIM;            // (N, K*D)
    float* out_loss = out_code + (size_t)NROWS * KST * DDIM; // scalar

    qprep<<<1, 32>>>();
    qmain<<<NROWS, 256>>>(h_in, Wp, bp, Wi, bi, temp, u, p, out_q, out_code);
    qfinal<<<1, 1024>>>(out_loss);
}

// round 10
// speedup vs baseline: 2.2489x; 2.2489x over previous
#include <cuda_runtime.h>
#include <cuda_bf16.h>
#include <math.h>

#define NROWS 65536
#define EDIM  1024
#define KST   4
#define DDIM  5
#define NBLK  304
#define WPB   8
#define NWARPS (NBLK * WPB)

// ---- device scratch / constants (no allocations allowed) ----
__device__ float g_shift[5];
__device__ float g_half_l[5];
__device__ float g_off_b[5];
__device__ float g_halfw[5];
__device__ float g_row_norm[NROWS];

__constant__ int c_lo[5] = {0, 0, 0, 1, 2};   // valid step index range per dim
__constant__ int c_hi[5] = {7, 7, 7, 6, 6};   // steps = idx - 4  ->  [-4..3]

// ---- prep: compute bound constants in double, matching numpy f64 -> f32 ----
__global__ void qprep() {
    int t = threadIdx.x;
    if (t < 5) {
        const double lev[5] = {8.0, 8.0, 8.0, 6.0, 5.0};
        double half_l = (lev[t] - 1.0) * (1.0 - 1e-3) / 2.0;
        int li = (int)lev[t];
        double off_b = (li % 2 == 1) ? 0.0 : 0.5;
        g_half_l[t] = (float)half_l;
        g_off_b[t]  = (float)off_b;
        g_shift[t]  = (float)tan(off_b / half_l);
        g_halfw[t]  = (float)(li / 2);
    }
}

// ---- main fused kernel: warp-per-row, persistent blocks ----
__global__ __launch_bounds__(256) void qmain(
    const float* __restrict__ h_in,
    const float* __restrict__ Wp,     // (K, D, E)
    const float* __restrict__ bp,     // (K, D)
    const float* __restrict__ Wi,     // (K, E, D)
    const float* __restrict__ bi,     // (K, E)
    const float* __restrict__ temp,   // (1,)
    const float* __restrict__ u,      // (K, N, D, C)
    const float* __restrict__ p,      // (N,)
    float* __restrict__ out_q,        // (N, E)
    float* __restrict__ out_code)     // (N, K*D)
{
    extern __shared__ float smem[];
    float* sWi = smem;                         // (K*D)*E, d-major transposed Wi
    float* sG  = smem + KST * DDIM * EDIM;     // WPB * 160 gumbels

    const int t    = threadIdx.x;
    const int lane = t & 31;
    const int warp = t >> 5;

    // ---- one-time per block: transpose Wi (K,E,D) -> sWi[(i*D+d)*E + e] ----
    for (int idx = t; idx < KST * EDIM * DDIM; idx += 256) {
        int i   = idx / (EDIM * DDIM);
        int rem = idx - i * (EDIM * DDIM);
        int e   = rem / DDIM;
        int d   = rem - e * DDIM;
        sWi[(i * DDIM + d) * EDIM + e] = Wi[idx];
    }
    __syncthreads();

    float te = temp[0];
    te = fmaxf(te * te, 1e-8f);
    const float inv_t2 = 1.0f / (te * te);

    float* sGw = sG + warp * 160;
    const int gwarp = blockIdx.x * WPB + warp;

    for (int row = gwarp; row < NROWS; row += NWARPS) {
        // ---- precompute gumbels (160 = K*D*C) in parallel across lanes ----
        #pragma unroll
        for (int kk = 0; kk < 5; kk++) {
            int idx = kk * 32 + lane;                  // 0..159
            int i   = idx / 40;
            int r40 = idx - i * 40;
            float uu = __ldcs(u + ((size_t)i * NROWS + row) * 40 + r40);
            sGw[idx] = -logf(-logf(uu + 1e-20f) + 1e-20f);
        }
        __syncwarp();

        // ---- load residual, coalesced float4 (lane owns e = jj*128 + lane*4 ..+3) ----
        const float4* hrow = (const float4*)(h_in + (size_t)row * EDIM);
        float4 rv[8];
        float hh = 0.f;
        #pragma unroll
        for (int jj = 0; jj < 8; jj++) {
            float4 v = __ldcs(hrow + jj * 32 + lane);
            rv[jj] = v;
            hh += v.x * v.x + v.y * v.y + v.z * v.z + v.w * v.w;
        }

        const float pr = __ldg(p + row);
        float ssq_sel = 0.f;
        bool  any_sel = false;

        #pragma unroll
        for (int i = 0; i < KST; i++) {
            // ---- projection: pd[d] = sum_e Wp[i][d][e] * r[e] (warp reduce) ----
            float pd[5];
            const float* wpb_ = Wp + (size_t)i * DDIM * EDIM;
            #pragma unroll
            for (int d = 0; d < 5; d++) {
                const float4* wr = (const float4*)(wpb_ + d * EDIM);
                float s = 0.f;
                #pragma unroll
                for (int jj = 0; jj < 8; jj++) {
                    float4 w = wr[jj * 32 + lane];
                    s += w.x * rv[jj].x + w.y * rv[jj].y + w.z * rv[jj].z + w.w * rv[jj].w;
                }
                pd[d] = s;
            }
            #pragma unroll
            for (int d = 0; d < 5; d++) {
                #pragma unroll
                for (int off = 16; off; off >>= 1)
                    pd[d] += __shfl_xor_sync(0xffffffffu, pd[d], off);
            }

            // ---- quantize: lanes 0..4 handle one dim each ----
            float zq = 0.f;
            if (lane < 5) {
                float h = (lane == 0) ? pd[0] : (lane == 1) ? pd[1] :
                          (lane == 2) ? pd[2] : (lane == 3) ? pd[3] : pd[4];
                h += __ldg(bp + i * DDIM + lane);
                float z = tanhf(h + g_shift[lane]) * g_half_l[lane] - g_off_b[lane];

                const int lo = c_lo[lane], hi = c_hi[lane];
                const float* gp = sGw + i * 40 + lane * 8;
                float best = -INFINITY;
                int bc = lo;
                #pragma unroll
                for (int c = 0; c < 8; c++) {
                    if (c >= lo && c <= hi) {
                        float df  = z - (float)(c - 4);
                        float val = -(df * df) * inv_t2 + gp[c];
                        if (val > best) { best = val; bc = c; }  // first-max tie-break
                    }
                }
                zq = (float)(bc - 4) / g_halfw[lane];
                __stcs(out_code + (size_t)row * (KST * DDIM) + i * DDIM + lane, zq);
            }
            const float z0 = __shfl_sync(0xffffffffu, zq, 0);
            const float z1 = __shfl_sync(0xffffffffu, zq, 1);
            const float z2 = __shfl_sync(0xffffffffu, zq, 2);
            const float z3 = __shfl_sync(0xffffffffu, zq, 3);
            const float z4 = __shfl_sync(0xffffffffu, zq, 4);

            // ---- inverse projection from smem (d-major, conflict-free LDS.128) ----
            const float4* s0 = (const float4*)(sWi + (i * DDIM + 0) * EDIM);
            const float4* s1 = (const float4*)(sWi + (i * DDIM + 1) * EDIM);
            const float4* s2 = (const float4*)(sWi + (i * DDIM + 2) * EDIM);
            const float4* s3 = (const float4*)(sWi + (i * DDIM + 3) * EDIM);
            const float4* s4 = (const float4*)(sWi + (i * DDIM + 4) * EDIM);
            const float4* bv4 = (const float4*)(bi + (size_t)i * EDIM);
            #pragma unroll
            for (int jj = 0; jj < 8; jj++) {
                int e4 = jj * 32 + lane;
                float4 w0 = s0[e4];
                float4 w1 = s1[e4];
                float4 w2 = s2[e4];
                float4 w3 = s3[e4];
                float4 w4 = s4[e4];
                float4 bb = bv4[e4];
                rv[jj].x -= bb.x + w0.x * z0 + w1.x * z1 + w2.x * z2 + w3.x * z3 + w4.x * z4;
                rv[jj].y -= bb.y + w0.y * z0 + w1.y * z1 + w2.y * z2 + w3.y * z3 + w4.y * z4;
                rv[jj].z -= bb.z + w0.z * z0 + w1.z * z1 + w2.z * z2 + w3.z * z3 + w4.z * z4;
                rv[jj].w -= bb.w + w0.w * z0 + w1.w * z1 + w2.w * z2 + w3.w * z3 + w4.w * z4;
            }

            // ---- loss selection: h_in - q_mix == residual after selected stage ----
            bool sel = (((float)i * 0.25f) < pr) && (pr <= ((float)(i + 1) * 0.25f));
            if (sel) {
                float s = 0.f;
                #pragma unroll
                for (int jj = 0; jj < 8; jj++)
                    s += rv[jj].x * rv[jj].x + rv[jj].y * rv[jj].y +
                         rv[jj].z * rv[jj].z + rv[jj].w * rv[jj].w;
                ssq_sel = s;
                any_sel = true;
            }
        }

        // ---- q = h0 - r_final (reload h0, streaming) + per-row norm ----
        float4* qrow = (float4*)(out_q + (size_t)row * EDIM);
        #pragma unroll
        for (int jj = 0; jj < 8; jj++) {
            float4 h0 = __ldcs(hrow + jj * 32 + lane);
            float4 qv = make_float4(h0.x - rv[jj].x, h0.y - rv[jj].y,
                                    h0.z - rv[jj].z, h0.w - rv[jj].w);
            __stcs(qrow + jj * 32 + lane, qv);
        }

        float ss = any_sel ? ssq_sel : hh;
        #pragma unroll
        for (int off = 16; off; off >>= 1)
            ss += __shfl_xor_sync(0xffffffffu, ss, off);
        if (lane == 0) g_row_norm[row] = sqrtf(ss);
    }
}

// ---- deterministic mean of per-row norms ----
__global__ __launch_bounds__(1024) void qfinal(float* __restrict__ out_loss) {
    __shared__ float sh[1024];
    float s = 0.f;
    for (int idx = threadIdx.x; idx < NROWS; idx += 1024) s += g_row_norm[idx];
    sh[threadIdx.x] = s;
    __syncthreads();
    for (int stride = 512; stride; stride >>= 1) {
        if (threadIdx.x < (unsigned)stride) sh[threadIdx.x] += sh[threadIdx.x + stride];
        __syncthreads();
    }
    if (threadIdx.x == 0) out_loss[0] = sh[0] / (float)NROWS;
}

extern "C" void kernel_launch(void* const* d_in, const int* in_sizes, int n_in,
                              void* d_out, int out_size) {
    const float* h_in = (const float*)d_in[0];
    const float* Wp   = (const float*)d_in[1];
    const float* bp   = (const float*)d_in[2];
    const float* Wi   = (const float*)d_in[3];
    const float* bi   = (const float*)d_in[4];
    const float* temp = (const float*)d_in[5];
    const float* u    = (const float*)d_in[6];
    const float* p    = (const float*)d_in[7];

    float* out      = (float*)d_out;
    float* out_q    = out;                                   // (N, E)
    float* out_code = out + (size_t)NROWS * EDIM;            // (N, K*D)
    float* out_loss = out_code + (size_t)NROWS * KST * DDIM; // scalar

    const int smem_bytes = (KST * DDIM * EDIM + WPB * 160) * (int)sizeof(float); // 87040
    cudaFuncSetAttribute(qmain, cudaFuncAttributeMaxDynamicSharedMemorySize, smem_bytes);

    qprep<<<1, 32>>>();
    qmain<<<NBLK, 256, smem_bytes>>>(h_in, Wp, bp, Wi, bi, temp, u, p, out_q, out_code);
    qfinal<<<1, 1024>>>(out_loss);
}

// round 12
// speedup vs baseline: 3.2375x; 1.4396x over previous
#include <cuda_runtime.h>
#include <cuda_bf16.h>
#include <math.h>

#define NROWS 65536
#define EDIM  1024
#define KST   4
#define DDIM  5
#define NBLK  304
#define WPB   8
#define NWARPS (NBLK * WPB)

typedef unsigned long long ull;

__device__ float g_row_norm[NROWS];

__constant__ int c_lo[5] = {0, 0, 0, 1, 2};   // valid step index range per dim
__constant__ int c_hi[5] = {7, 7, 7, 6, 6};   // steps = idx - 4  ->  [-4..3]

// ---- packed f32x2 helpers (ptxas never emits FFMA2 from C++) ----
__device__ __forceinline__ ull pk2(float lo, float hi) {
    ull r; asm("mov.b64 %0, {%1, %2};" : "=l"(r) : "f"(lo), "f"(hi)); return r;
}
__device__ __forceinline__ void upk2(ull v, float& a, float& b) {
    asm("mov.b64 {%0, %1}, %2;" : "=f"(a), "=f"(b) : "l"(v));
}
__device__ __forceinline__ ull ffma2_(ull a, ull b, ull c) {
    ull d; asm("fma.rn.f32x2 %0, %1, %2, %3;" : "=l"(d) : "l"(a), "l"(b), "l"(c));
    return d;
}

// ---- main fused kernel: 2 rows per warp, persistent blocks ----
__global__ __launch_bounds__(256, 2) void qmain(
    const float* __restrict__ h_in,
    const float* __restrict__ Wp,     // (K, D, E)
    const float* __restrict__ bp,     // (K, D)
    const float* __restrict__ Wi,     // (K, E, D)
    const float* __restrict__ bi,     // (K, E)
    const float* __restrict__ temp,   // (1,)
    const float* __restrict__ u,      // (K, N, D, C)
    const float* __restrict__ p,      // (N,)
    float* __restrict__ out_q,        // (N, E)
    float* __restrict__ out_code)     // (N, K*D)
{
    extern __shared__ float smem[];
    float* sWi = smem;                         // (K*D)*E, d-major transposed Wi
    float* sG  = smem + KST * DDIM * EDIM;     // WPB * 320 gumbels (2 rows/warp)

    const int t    = threadIdx.x;
    const int lane = t & 31;
    const int warp = t >> 5;

    // ---- one-time per block: transpose Wi (K,E,D) -> sWi[(i*D+d)*E + e] ----
    for (int idx = t; idx < KST * EDIM * DDIM; idx += 256) {
        int i   = idx / (EDIM * DDIM);
        int rem = idx - i * (EDIM * DDIM);
        int e   = rem / DDIM;
        int d   = rem - e * DDIM;
        sWi[(i * DDIM + d) * EDIM + e] = Wi[idx];
    }
    __syncthreads();

    float te = temp[0];
    te = fmaxf(te * te, 1e-8f);
    const float inv_t2 = 1.0f / (te * te);
    const ull NEG1 = pk2(-1.0f, -1.0f);

    // ---- per-lane quantizer constants (lanes 0..4 -> rowA dims, 8..12 -> rowB) ----
    const bool qlaneA = (lane < 5);
    const bool qlaneB = (lane >= 8 && lane < 13);
    const int  qd     = qlaneA ? lane : (qlaneB ? (lane - 8) : 0);
    float k_shift = 0.f, k_half_l = 1.f, k_off = 0.f, k_halfw = 1.f;
    if (qlaneA || qlaneB) {
        double lev = (qd < 3) ? 8.0 : ((qd == 3) ? 6.0 : 5.0);
        double half_l = (lev - 1.0) * (1.0 - 1e-3) / 2.0;
        double off_b  = (((int)lev) & 1) ? 0.0 : 0.5;
        k_half_l = (float)half_l;
        k_off    = (float)off_b;
        k_shift  = (float)tan(off_b / half_l);
        k_halfw  = (float)((int)lev / 2);
    }
    const int q_lo = c_lo[qd], q_hi = c_hi[qd];

    float* sGw = sG + warp * 320;
    const int gwarp = blockIdx.x * WPB + warp;

    for (int rowA = 2 * gwarp; rowA < NROWS; rowA += 2 * NWARPS) {
        const int rowB = rowA + 1;

        // ---- precompute gumbels for both rows (coalesced) ----
        #pragma unroll
        for (int kk = 0; kk < 10; kk++) {
            int idx = kk * 32 + lane;                   // 0..319
            int rsel = idx / 160;                       // 0=A, 1=B
            int j    = idx - rsel * 160;
            int i    = j / 40;
            int r40  = j - i * 40;
            float uu = __ldcs(u + ((size_t)i * NROWS + (rowA + rsel)) * 40 + r40);
            sGw[idx] = -logf(-logf(uu + 1e-20f) + 1e-20f);
        }
        __syncwarp();

        // ---- load residuals (packed f32x2 in registers) ----
        const float4* hA = (const float4*)(h_in + (size_t)rowA * EDIM);
        const float4* hB = (const float4*)(h_in + (size_t)rowB * EDIM);
        ull rA[16], rB[16];
        ull hhAp = 0ull, hhBp = 0ull;
        #pragma unroll
        for (int jj = 0; jj < 8; jj++) {
            float4 va = hA[jj * 32 + lane];
            float4 vb = hB[jj * 32 + lane];
            rA[2*jj]   = pk2(va.x, va.y);  rA[2*jj+1] = pk2(va.z, va.w);
            rB[2*jj]   = pk2(vb.x, vb.y);  rB[2*jj+1] = pk2(vb.z, vb.w);
            hhAp = ffma2_(rA[2*jj], rA[2*jj], hhAp);
            hhAp = ffma2_(rA[2*jj+1], rA[2*jj+1], hhAp);
            hhBp = ffma2_(rB[2*jj], rB[2*jj], hhBp);
            hhBp = ffma2_(rB[2*jj+1], rB[2*jj+1], hhBp);
        }
        float hhA, hhB;
        { float x, y; upk2(hhAp, x, y); hhA = x + y; upk2(hhBp, x, y); hhB = x + y; }

        const float prA = __ldg(p + rowA);
        const float prB = __ldg(p + rowB);
        float ssqA = 0.f, ssqB = 0.f;
        bool  selA = false, selB = false;

        #pragma unroll
        for (int i = 0; i < KST; i++) {
            // ---- projection: shared weight loads feed both rows ----
            float pdA[5], pdB[5];
            const float* wpb_ = Wp + (size_t)i * DDIM * EDIM;
            #pragma unroll
            for (int d = 0; d < 5; d++) {
                const float4* wr = (const float4*)(wpb_ + d * EDIM);
                ull aA = 0ull, aB = 0ull;
                #pragma unroll
                for (int jj = 0; jj < 8; jj++) {
                    float4 w = wr[jj * 32 + lane];
                    ull wl = pk2(w.x, w.y), wh = pk2(w.z, w.w);
                    aA = ffma2_(wl, rA[2*jj], aA);
                    aA = ffma2_(wh, rA[2*jj+1], aA);
                    aB = ffma2_(wl, rB[2*jj], aB);
                    aB = ffma2_(wh, rB[2*jj+1], aB);
                }
                float x, y;
                upk2(aA, x, y); pdA[d] = x + y;
                upk2(aB, x, y); pdB[d] = x + y;
            }
            #pragma unroll
            for (int d = 0; d < 5; d++) {
                #pragma unroll
                for (int off = 16; off; off >>= 1) {
                    pdA[d] += __shfl_xor_sync(0xffffffffu, pdA[d], off);
                    pdB[d] += __shfl_xor_sync(0xffffffffu, pdB[d], off);
                }
            }

            // ---- quantize: lanes 0..4 do rowA, lanes 8..12 do rowB ----
            float zq = 0.f;
            if (qlaneA || qlaneB) {
                float h = qlaneA ?
                    ((qd==0)?pdA[0]:(qd==1)?pdA[1]:(qd==2)?pdA[2]:(qd==3)?pdA[3]:pdA[4]) :
                    ((qd==0)?pdB[0]:(qd==1)?pdB[1]:(qd==2)?pdB[2]:(qd==3)?pdB[3]:pdB[4]);
                h += __ldg(bp + i * DDIM + qd);
                float z = tanhf(h + k_shift) * k_half_l - k_off;

                const float* gp = sGw + (qlaneB ? 160 : 0) + i * 40 + qd * 8;
                float best = -INFINITY;
                int bc = q_lo;
                #pragma unroll
                for (int c = 0; c < 8; c++) {
                    if (c >= q_lo && c <= q_hi) {
                        float df  = z - (float)(c - 4);
                        float val = -(df * df) * inv_t2 + gp[c];
                        if (val > best) { best = val; bc = c; }  // first-max tie-break
                    }
                }
                zq = (float)(bc - 4) / k_halfw;
                size_t row = qlaneA ? (size_t)rowA : (size_t)rowB;
                __stcs(out_code + row * (KST * DDIM) + i * DDIM + qd, zq);
            }
            const ull zA0 = pk2(__shfl_sync(0xffffffffu, zq, 0), __shfl_sync(0xffffffffu, zq, 0));
            const ull zA1 = pk2(__shfl_sync(0xffffffffu, zq, 1), __shfl_sync(0xffffffffu, zq, 1));
            const ull zA2 = pk2(__shfl_sync(0xffffffffu, zq, 2), __shfl_sync(0xffffffffu, zq, 2));
            const ull zA3 = pk2(__shfl_sync(0xffffffffu, zq, 3), __shfl_sync(0xffffffffu, zq, 3));
            const ull zA4 = pk2(__shfl_sync(0xffffffffu, zq, 4), __shfl_sync(0xffffffffu, zq, 4));
            const ull zB0 = pk2(__shfl_sync(0xffffffffu, zq, 8), __shfl_sync(0xffffffffu, zq, 8));
            const ull zB1 = pk2(__shfl_sync(0xffffffffu, zq, 9), __shfl_sync(0xffffffffu, zq, 9));
            const ull zB2 = pk2(__shfl_sync(0xffffffffu, zq, 10), __shfl_sync(0xffffffffu, zq, 10));
            const ull zB3 = pk2(__shfl_sync(0xffffffffu, zq, 11), __shfl_sync(0xffffffffu, zq, 11));
            const ull zB4 = pk2(__shfl_sync(0xffffffffu, zq, 12), __shfl_sync(0xffffffffu, zq, 12));

            // ---- inverse projection from smem, weights shared by both rows ----
            const float4* s0 = (const float4*)(sWi + (i * DDIM + 0) * EDIM);
            const float4* s1 = (const float4*)(sWi + (i * DDIM + 1) * EDIM);
            const float4* s2 = (const float4*)(sWi + (i * DDIM + 2) * EDIM);
            const float4* s3 = (const float4*)(sWi + (i * DDIM + 3) * EDIM);
            const float4* s4 = (const float4*)(sWi + (i * DDIM + 4) * EDIM);
            const float4* bv4 = (const float4*)(bi + (size_t)i * EDIM);
            #pragma unroll
            for (int jj = 0; jj < 8; jj++) {
                int e4 = jj * 32 + lane;
                float4 w0 = s0[e4], w1 = s1[e4], w2 = s2[e4], w3 = s3[e4], w4 = s4[e4];
                float4 bb = bv4[e4];
                ull w0l = pk2(w0.x,w0.y), w0h = pk2(w0.z,w0.w);
                ull w1l = pk2(w1.x,w1.y), w1h = pk2(w1.z,w1.w);
                ull w2l = pk2(w2.x,w2.y), w2h = pk2(w2.z,w2.w);
                ull w3l = pk2(w3.x,w3.y), w3h = pk2(w3.z,w3.w);
                ull w4l = pk2(w4.x,w4.y), w4h = pk2(w4.z,w4.w);
                ull bbl = pk2(bb.x,bb.y), bbh = pk2(bb.z,bb.w);

                ull tl = bbl;
                tl = ffma2_(w0l, zA0, tl); tl = ffma2_(w1l, zA1, tl);
                tl = ffma2_(w2l, zA2, tl); tl = ffma2_(w3l, zA3, tl);
                tl = ffma2_(w4l, zA4, tl);
                rA[2*jj] = ffma2_(tl, NEG1, rA[2*jj]);
                ull th = bbh;
                th = ffma2_(w0h, zA0, th); th = ffma2_(w1h, zA1, th);
                th = ffma2_(w2h, zA2, th); th = ffma2_(w3h, zA3, th);
                th = ffma2_(w4h, zA4, th);
                rA[2*jj+1] = ffma2_(th, NEG1, rA[2*jj+1]);

                ull ul = bbl;
                ul = ffma2_(w0l, zB0, ul); ul = ffma2_(w1l, zB1, ul);
                ul = ffma2_(w2l, zB2, ul); ul = ffma2_(w3l, zB3, ul);
                ul = ffma2_(w4l, zB4, ul);
                rB[2*jj] = ffma2_(ul, NEG1, rB[2*jj]);
                ull uh = bbh;
                uh = ffma2_(w0h, zB0, uh); uh = ffma2_(w1h, zB1, uh);
                uh = ffma2_(w2h, zB2, uh); uh = ffma2_(w3h, zB3, uh);
                uh = ffma2_(w4h, zB4, uh);
                rB[2*jj+1] = ffma2_(uh, NEG1, rB[2*jj+1]);
            }

            // ---- loss selection: h_in - q_mix == residual after selected stage ----
            const float tlo = (float)i * 0.25f, thi = (float)(i + 1) * 0.25f;
            if ((tlo < prA) && (prA <= thi)) {
                ull sp = 0ull;
                #pragma unroll
                for (int k = 0; k < 16; k++) sp = ffma2_(rA[k], rA[k], sp);
                float x, y; upk2(sp, x, y); ssqA = x + y; selA = true;
            }
            if ((tlo < prB) && (prB <= thi)) {
                ull sp = 0ull;
                #pragma unroll
                for (int k = 0; k < 16; k++) sp = ffma2_(rB[k], rB[k], sp);
                float x, y; upk2(sp, x, y); ssqB = x + y; selB = true;
            }
        }

        // ---- q = h0 - r_final (h reread should hit L2) ----
        float4* qA = (float4*)(out_q + (size_t)rowA * EDIM);
        float4* qB = (float4*)(out_q + (size_t)rowB * EDIM);
        #pragma unroll
        for (int jj = 0; jj < 8; jj++) {
            float4 ha = hA[jj * 32 + lane];
            float4 hb = hB[jj * 32 + lane];
            ull qal = ffma2_(rA[2*jj],   NEG1, pk2(ha.x, ha.y));
            ull qah = ffma2_(rA[2*jj+1], NEG1, pk2(ha.z, ha.w));
            ull qbl = ffma2_(rB[2*jj],   NEG1, pk2(hb.x, hb.y));
            ull qbh = ffma2_(rB[2*jj+1], NEG1, pk2(hb.z, hb.w));
            float4 qa, qb;
            upk2(qal, qa.x, qa.y); upk2(qah, qa.z, qa.w);
            upk2(qbl, qb.x, qb.y); upk2(qbh, qb.z, qb.w);
            __stcs(qA + jj * 32 + lane, qa);
            __stcs(qB + jj * 32 + lane, qb);
        }

        // ---- per-row norms ----
        float sa = selA ? ssqA : hhA;
        float sb = selB ? ssqB : hhB;
        #pragma unroll
        for (int off = 16; off; off >>= 1) {
            sa += __shfl_xor_sync(0xffffffffu, sa, off);
            sb += __shfl_xor_sync(0xffffffffu, sb, off);
        }
        if (lane == 0) {
            g_row_norm[rowA] = sqrtf(sa);
            g_row_norm[rowB] = sqrtf(sb);
        }
    }
}

// ---- deterministic mean of per-row norms ----
__global__ __launch_bounds__(1024) void qfinal(float* __restrict__ out_loss) {
    __shared__ float sh[1024];
    float s = 0.f;
    for (int idx = threadIdx.x; idx < NROWS; idx += 1024) s += g_row_norm[idx];
    sh[threadIdx.x] = s;
    __syncthreads();
    for (int stride = 512; stride; stride >>= 1) {
        if (threadIdx.x < (unsigned)stride) sh[threadIdx.x] += sh[threadIdx.x + stride];
        __syncthreads();
    }
    if (threadIdx.x == 0) out_loss[0] = sh[0] / (float)NROWS;
}

extern "C" void kernel_launch(void* const* d_in, const int* in_sizes, int n_in,
                              void* d_out, int out_size) {
    const float* h_in = (const float*)d_in[0];
    const float* Wp   = (const float*)d_in[1];
    const float* bp   = (const float*)d_in[2];
    const float* Wi   = (const float*)d_in[3];
    const float* bi   = (const float*)d_in[4];
    const float* temp = (const float*)d_in[5];
    const float* u    = (const float*)d_in[6];
    const float* p    = (const float*)d_in[7];

    float* out      = (float*)d_out;
    float* out_q    = out;                                   // (N, E)
    float* out_code = out + (size_t)NROWS * EDIM;            // (N, K*D)
    float* out_loss = out_code + (size_t)NROWS * KST * DDIM; // scalar

    const int smem_bytes = (KST * DDIM * EDIM + WPB * 320) * (int)sizeof(float); // 92160
    cudaFuncSetAttribute(qmain, cudaFuncAttributeMaxDynamicSharedMemorySize, smem_bytes);

    qmain<<<NBLK, 256, smem_bytes>>>(h_in, Wp, bp, Wi, bi, temp, u, p, out_q, out_code);
    qfinal<<<1, 1024>>>(out_loss);
}